// round 4
// baseline (speedup 1.0000x reference)
#include <cuda_runtime.h>
#include <math.h>

#define PASSES          4          // rows per warp = PASSES * 4
#define ROWS_PER_WARP   16
#define WARPS_PER_BLOCK 8
#define THREADS         256
#define MAX_BLOCKS      8192

__device__ double g_part[MAX_BLOCKS];
__device__ unsigned int g_count;    // zero at load; last block resets -> replay-safe

__device__ __forceinline__ float softplusf(float x) {
    return fmaxf(x, 0.0f) + log1pf(expf(-fabsf(x)));
}

// packed f32x2 helpers
__device__ __forceinline__ unsigned long long pack2(float lo, float hi) {
    unsigned long long r;
    asm("mov.b64 %0, {%1, %2};" : "=l"(r) : "f"(lo), "f"(hi));
    return r;
}
__device__ __forceinline__ void unpack2(unsigned long long v, float& lo, float& hi) {
    asm("mov.b64 {%0, %1}, %2;" : "=f"(lo), "=f"(hi) : "l"(v));
}
__device__ __forceinline__ unsigned long long fma2(unsigned long long a,
                                                   unsigned long long b,
                                                   unsigned long long c) {
    unsigned long long d;
    asm("fma.rn.f32x2 %0, %1, %2, %3;" : "=l"(d) : "l"(a), "l"(b), "l"(c));
    return d;
}
__device__ __forceinline__ unsigned long long mul2(unsigned long long a,
                                                   unsigned long long b) {
    unsigned long long d;
    asm("mul.rn.f32x2 %0, %1, %2;" : "=l"(d) : "l"(a), "l"(b));
    return d;
}
__device__ __forceinline__ unsigned long long add2(unsigned long long a,
                                                   unsigned long long b) {
    unsigned long long d;
    asm("add.rn.f32x2 %0, %1, %2;" : "=l"(d) : "l"(a), "l"(b));
    return d;
}

__global__ void __launch_bounds__(THREADS) sat_fused_kernel(
    const int* __restrict__ b1, const int* __restrict__ b2,
    const float* __restrict__ z1, const float* __restrict__ z2,
    const float* __restrict__ g1, const float* __restrict__ g2,
    float* __restrict__ out, int N)
{
    const int lane = threadIdx.x & 31;
    const int wib  = threadIdx.x >> 5;
    const int li   = lane & 7;        // lane within 8-lane row-group
    const int gr   = lane >> 3;       // row-group 0..3

    const int warpsPerStream = N / ROWS_PER_WARP;          // 4096
    const int gwarp  = blockIdx.x * WARPS_PER_BLOCK + wib;
    const int stream = (gwarp >= warpsPerStream) ? 1 : 0;
    const int wloc   = gwarp - stream * warpsPerStream;
    const int wbase  = wloc * ROWS_PER_WARP;               // first row

    const int*   b  = stream ? b2 : b1;
    const float* z  = stream ? z2 : z1;
    const float* gS = stream ? g2 : g1;   // self pairing
    const float* gC = stream ? g1 : g2;   // cross pairing

    // this warp's 16 batch ids (coalesced)
    int myb = (lane < ROWS_PER_WARP) ? b[wbase + lane] : 0;

    const float4* z4  = reinterpret_cast<const float4*>(z);
    const float4* gS4 = reinterpret_cast<const float4*>(gS);
    const float4* gC4 = reinterpret_cast<const float4*>(gC);

    unsigned long long res = 0;   // lane (li==p) keeps (dS,dC) of row wbase+p*4+gr

    #pragma unroll
    for (int p = 0; p < PASSES; ++p) {
        const int row  = wbase + p * 4 + gr;
        const int gidx = __shfl_sync(0xFFFFFFFFu, myb, p * 4 + gr);

        const float4* zr = z4  + (size_t)row  * 64 + li;   // lane stripe
        const float4* sr = gS4 + (size_t)gidx * 64 + li;
        const float4* cr = gC4 + (size_t)gidx * 64 + li;

        // 8 float4 per lane, stride 8 float4 (128B) -> coalesced per 8-lane group
        float4 zk[8], sk[8], ck[8];
        #pragma unroll
        for (int k = 0; k < 8; ++k) zk[k] = __ldcs(zr + 8 * k);   // stream z
        #pragma unroll
        for (int k = 0; k < 8; ++k) sk[k] = __ldg(sr + 8 * k);    // g: L1-resident
        #pragma unroll
        for (int k = 0; k < 8; ++k) ck[k] = __ldg(cr + 8 * k);

        unsigned long long vS = 0, vC = 0;
        #pragma unroll
        for (int k = 0; k < 8; ++k) {
            unsigned long long z0 = pack2(zk[k].x, zk[k].y);
            unsigned long long z1p = pack2(zk[k].z, zk[k].w);
            if (k == 0) {
                vS = mul2(z0, pack2(sk[k].x, sk[k].y));
                vC = mul2(z0, pack2(ck[k].x, ck[k].y));
            } else {
                vS = fma2(z0, pack2(sk[k].x, sk[k].y), vS);
                vC = fma2(z0, pack2(ck[k].x, ck[k].y), vC);
            }
            vS = fma2(z1p, pack2(sk[k].z, sk[k].w), vS);
            vC = fma2(z1p, pack2(ck[k].z, ck[k].w), vC);
        }
        float sx, sy, cx, cy;
        unpack2(vS, sx, sy); unpack2(vC, cx, cy);
        unsigned long long w = pack2(sx + sy, cx + cy);

        // 3-stage butterfly within the 8-lane group (4 rows reduce in parallel)
        #pragma unroll
        for (int off = 4; off > 0; off >>= 1)
            w = add2(w, __shfl_xor_sync(0xFFFFFFFFu, w, off));

        if (li == p) res = w;
    }

    // lanes with li < PASSES hold 16 distinct rows' (dS,dC); others hold (0,0) -> t==0
    float dS, dC;
    unpack2(res, dS, dC);
    float t = softplusf(-dC) - softplusf(-dS);     // LOG2 cancels in the diff
    double accd = (double)t * (double)t;

    #pragma unroll
    for (int off = 16; off > 0; off >>= 1)
        accd += __shfl_xor_sync(0xFFFFFFFFu, accd, off);

    __shared__ double sh[WARPS_PER_BLOCK];
    __shared__ int s_isLast;
    if (lane == 0) sh[wib] = accd;
    __syncthreads();

    if (threadIdx.x == 0) {
        double s = 0.0;
        #pragma unroll
        for (int i = 0; i < WARPS_PER_BLOCK; i++) s += sh[i];
        g_part[blockIdx.x] = s;
        __threadfence();
        unsigned int old = atomicAdd(&g_count, 1u);
        s_isLast = (old == gridDim.x - 1) ? 1 : 0;
    }
    __syncthreads();

    if (s_isLast) {
        const int grid = gridDim.x;
        const int half = grid >> 1;                 // first half = stream 0
        double s0 = 0.0, s1 = 0.0;
        volatile double* vp = g_part;
        for (int i = threadIdx.x; i < grid; i += THREADS) {
            double v = vp[i];
            if (i < half) s0 += v; else s1 += v;
        }
        #pragma unroll
        for (int off = 16; off > 0; off >>= 1) {
            s0 += __shfl_xor_sync(0xFFFFFFFFu, s0, off);
            s1 += __shfl_xor_sync(0xFFFFFFFFu, s1, off);
        }
        __shared__ double r0[WARPS_PER_BLOCK], r1[WARPS_PER_BLOCK];
        if (lane == 0) { r0[wib] = s0; r1[wib] = s1; }
        __syncthreads();
        if (threadIdx.x == 0) {
            double S0 = 0.0, S1 = 0.0;
            #pragma unroll
            for (int i = 0; i < WARPS_PER_BLOCK; i++) { S0 += r0[i]; S1 += r1[i]; }
            out[0] = (float)(sqrt(S0) + sqrt(S1));
            atomicExch(&g_count, 0u);
        }
    }
}

extern "C" void kernel_launch(void* const* d_in, const int* in_sizes, int n_in,
                              void* d_out, int out_size) {
    const int*   b1 = (const int*)d_in[0];
    const int*   b2 = (const int*)d_in[1];
    const float* z1 = (const float*)d_in[2];
    const float* z2 = (const float*)d_in[3];
    const float* g1 = (const float*)d_in[4];
    const float* g2 = (const float*)d_in[5];
    float* out = (float*)d_out;

    const int N = in_sizes[0];                                  // 65536
    const int rowsPerBlock = ROWS_PER_WARP * WARPS_PER_BLOCK;   // 128
    const int grid = (2 * N) / rowsPerBlock;                    // 1024

    sat_fused_kernel<<<grid, THREADS>>>(b1, b2, z1, z2, g1, g2, out, N);
}

// round 5
// speedup vs baseline: 1.1324x; 1.1324x over previous
#include <cuda_runtime.h>
#include <math.h>

#define ROWS_PER_BLOCK  128
#define THREADS         128
#define D               256
#define CHUNK           64                 // floats per K-chunk
#define CHUNK_Q         16                 // float4 per chunk
#define NCHUNK          (D / CHUNK)        // 4
#define ROW_STRIDE_Q    17                 // padded float4 stride (bank-conflict-free)
#define SMEM_BUF_Q      (ROWS_PER_BLOCK * ROW_STRIDE_Q)
#define MAX_BLOCKS      8192

__device__ double g_part[MAX_BLOCKS];
__device__ unsigned int g_count;           // zero at load; last block resets -> replay-safe

__device__ __forceinline__ float softplusf(float x) {
    return fmaxf(x, 0.0f) + log1pf(expf(-fabsf(x)));
}

// packed f32x2 helpers
__device__ __forceinline__ unsigned long long pack2(float lo, float hi) {
    unsigned long long r;
    asm("mov.b64 %0, {%1, %2};" : "=l"(r) : "f"(lo), "f"(hi));
    return r;
}
__device__ __forceinline__ void unpack2(unsigned long long v, float& lo, float& hi) {
    asm("mov.b64 {%0, %1}, %2;" : "=f"(lo), "=f"(hi) : "l"(v));
}
__device__ __forceinline__ unsigned long long fma2(unsigned long long a,
                                                   unsigned long long b,
                                                   unsigned long long c) {
    unsigned long long d;
    asm("fma.rn.f32x2 %0, %1, %2, %3;" : "=l"(d) : "l"(a), "l"(b), "l"(c));
    return d;
}

__device__ __forceinline__ void cp_async16(unsigned int smem_addr, const void* gptr) {
    asm volatile("cp.async.cg.shared.global [%0], [%1], 16;" :: "r"(smem_addr), "l"(gptr));
}
__device__ __forceinline__ void cp_commit() {
    asm volatile("cp.async.commit_group;");
}
template <int N_>
__device__ __forceinline__ void cp_wait() {
    asm volatile("cp.async.wait_group %0;" :: "n"(N_));
}

__global__ void __launch_bounds__(THREADS) sat_fused_kernel(
    const int* __restrict__ b1, const int* __restrict__ b2,
    const float* __restrict__ z1, const float* __restrict__ z2,
    const float* __restrict__ g1, const float* __restrict__ g2,
    float* __restrict__ out, int N)
{
    extern __shared__ float4 zbuf[];                  // [2][SMEM_BUF_Q]
    const int tid  = threadIdx.x;
    const int lane = tid & 31;
    const int wib  = tid >> 5;

    const int blocksPerStream = N / ROWS_PER_BLOCK;   // 512
    const int stream = (blockIdx.x >= blocksPerStream) ? 1 : 0;
    const int blk    = blockIdx.x - stream * blocksPerStream;
    const int base   = blk * ROWS_PER_BLOCK;

    const int*   b  = stream ? b2 : b1;
    const float* z  = stream ? z2 : z1;
    const float* gS = stream ? g2 : g1;               // self pairing
    const float* gC = stream ? g1 : g2;               // cross pairing

    const int gidx = b[base + tid];                   // my row's graph id
    const float4* gS4 = reinterpret_cast<const float4*>(gS) + (size_t)gidx * 64;
    const float4* gC4 = reinterpret_cast<const float4*>(gC) + (size_t)gidx * 64;
    const float4* z4  = reinterpret_cast<const float4*>(z) + (size_t)base * 64;

    unsigned int smem_base;
    {
        void* p = (void*)zbuf;
        smem_base = (unsigned int)__cvta_generic_to_shared(p);
    }

    // stage chunk c into buffer buf: 128 rows x 16 float4, coalesced
    auto stage = [&](int c, int buf) {
        const unsigned int sbase = smem_base + (unsigned int)buf * SMEM_BUF_Q * 16u;
        #pragma unroll
        for (int j = 0; j < 16; ++j) {
            const int i   = j * 128 + tid;            // 0..2047
            const int row = i >> 4;
            const int q   = i & 15;
            cp_async16(sbase + (unsigned int)(row * ROW_STRIDE_Q + q) * 16u,
                       (const void*)(z4 + (size_t)row * 64 + c * CHUNK_Q + q));
        }
        cp_commit();
    };

    unsigned long long vS = 0, vC = 0;                // packed (even,odd) partial dots

    stage(0, 0);
    #pragma unroll
    for (int c = 0; c < NCHUNK; ++c) {
        if (c + 1 < NCHUNK) stage(c + 1, (c + 1) & 1);
        if (c + 1 < NCHUNK) cp_wait<1>(); else cp_wait<0>();
        __syncthreads();

        const float4* zb = zbuf + (c & 1) * SMEM_BUF_Q + tid * ROW_STRIDE_Q;
        #pragma unroll
        for (int q = 0; q < CHUNK_Q; ++q) {
            float4 zv = zb[q];
            float4 sv = __ldg(gS4 + c * CHUNK_Q + q); // warp-uniform -> L1 broadcast
            float4 cv = __ldg(gC4 + c * CHUNK_Q + q);
            unsigned long long zlo = pack2(zv.x, zv.y), zhi = pack2(zv.z, zv.w);
            vS = fma2(zlo, pack2(sv.x, sv.y), vS);
            vS = fma2(zhi, pack2(sv.z, sv.w), vS);
            vC = fma2(zlo, pack2(cv.x, cv.y), vC);
            vC = fma2(zhi, pack2(cv.z, cv.w), vC);
        }
        __syncthreads();                              // before next-next stage reuses buffer
    }

    float sx, sy, cx, cy;
    unpack2(vS, sx, sy); unpack2(vC, cx, cy);
    const float dS = sx + sy, dC = cx + cy;
    const float t = softplusf(-dC) - softplusf(-dS);  // LOG2 cancels in the diff
    double accd = (double)t * (double)t;

    // block reduction (4 warps)
    #pragma unroll
    for (int off = 16; off > 0; off >>= 1)
        accd += __shfl_xor_sync(0xFFFFFFFFu, accd, off);

    __shared__ double sh[THREADS / 32];
    __shared__ int s_isLast;
    if (lane == 0) sh[wib] = accd;
    __syncthreads();

    if (tid == 0) {
        double s = sh[0] + sh[1] + sh[2] + sh[3];
        g_part[blockIdx.x] = s;
        __threadfence();
        unsigned int old = atomicAdd(&g_count, 1u);
        s_isLast = (old == gridDim.x - 1) ? 1 : 0;
    }
    __syncthreads();

    if (s_isLast) {
        const int grid = gridDim.x;
        const int half = grid >> 1;                   // first half = stream 0
        double s0 = 0.0, s1 = 0.0;
        volatile double* vp = g_part;
        for (int i = tid; i < grid; i += THREADS) {
            double v = vp[i];
            if (i < half) s0 += v; else s1 += v;
        }
        #pragma unroll
        for (int off = 16; off > 0; off >>= 1) {
            s0 += __shfl_xor_sync(0xFFFFFFFFu, s0, off);
            s1 += __shfl_xor_sync(0xFFFFFFFFu, s1, off);
        }
        __shared__ double r0[THREADS / 32], r1[THREADS / 32];
        if (lane == 0) { r0[wib] = s0; r1[wib] = s1; }
        __syncthreads();
        if (tid == 0) {
            double S0 = r0[0] + r0[1] + r0[2] + r0[3];
            double S1 = r1[0] + r1[1] + r1[2] + r1[3];
            out[0] = (float)(sqrt(S0) + sqrt(S1));
            atomicExch(&g_count, 0u);                 // reset for next graph replay
        }
    }
}

extern "C" void kernel_launch(void* const* d_in, const int* in_sizes, int n_in,
                              void* d_out, int out_size) {
    const int*   b1 = (const int*)d_in[0];
    const int*   b2 = (const int*)d_in[1];
    const float* z1 = (const float*)d_in[2];
    const float* z2 = (const float*)d_in[3];
    const float* g1 = (const float*)d_in[4];
    const float* g2 = (const float*)d_in[5];
    float* out = (float*)d_out;

    const int N = in_sizes[0];                        // 65536
    const int grid = (2 * N) / ROWS_PER_BLOCK;        // 1024
    const int smemBytes = 2 * SMEM_BUF_Q * 16;        // 69,632 B

    static int attrDone = 0;
    if (!attrDone) {
        cudaFuncSetAttribute(sat_fused_kernel,
                             cudaFuncAttributeMaxDynamicSharedMemorySize, smemBytes);
        attrDone = 1;
    }
    sat_fused_kernel<<<grid, THREADS, smemBytes>>>(b1, b2, z1, z2, g1, g2, out, N);
}

// round 7
// speedup vs baseline: 1.2565x; 1.1096x over previous
#include <cuda_runtime.h>
#include <math.h>

#define THREADS         128
#define WARPS           4
#define ROWS_PER_WARP   32
#define CHUNK_Q         8                  // float4 per chunk per row
#define NCHUNK          8                  // 8 chunks x 32 floats = D=256
#define WARP_BUF_Q      (ROWS_PER_WARP * CHUNK_Q)      // 256 float4 = 4KB
#define MAX_BLOCKS      8192

__device__ double g_part[MAX_BLOCKS];
__device__ unsigned int g_count;           // zero at load; last block resets -> replay-safe

__device__ __forceinline__ float softplusf(float x) {
    return fmaxf(x, 0.0f) + log1pf(expf(-fabsf(x)));
}

// packed f32x2 helpers
__device__ __forceinline__ unsigned long long pack2(float lo, float hi) {
    unsigned long long r;
    asm("mov.b64 %0, {%1, %2};" : "=l"(r) : "f"(lo), "f"(hi));
    return r;
}
__device__ __forceinline__ void unpack2(unsigned long long v, float& lo, float& hi) {
    asm("mov.b64 {%0, %1}, %2;" : "=f"(lo), "=f"(hi) : "l"(v));
}
__device__ __forceinline__ unsigned long long fma2(unsigned long long a,
                                                   unsigned long long b,
                                                   unsigned long long c) {
    unsigned long long d;
    asm("fma.rn.f32x2 %0, %1, %2, %3;" : "=l"(d) : "l"(a), "l"(b), "l"(c));
    return d;
}

__device__ __forceinline__ void cp_async16(unsigned int smem_addr, const void* gptr) {
    asm volatile("cp.async.cg.shared.global [%0], [%1], 16;" :: "r"(smem_addr), "l"(gptr));
}
__device__ __forceinline__ void cp_commit() {
    asm volatile("cp.async.commit_group;");
}
template <int N_>
__device__ __forceinline__ void cp_wait() {
    asm volatile("cp.async.wait_group %0;" :: "n"(N_));
}

__global__ void __launch_bounds__(THREADS, 7) sat_fused_kernel(
    const int* __restrict__ b1, const int* __restrict__ b2,
    const float* __restrict__ z1, const float* __restrict__ z2,
    const float* __restrict__ g1, const float* __restrict__ g2,
    float* __restrict__ out, int N)
{
    extern __shared__ float4 zbuf[];                  // [WARPS][2][WARP_BUF_Q]
    const int tid  = threadIdx.x;
    const int lane = tid & 31;
    const int wib  = tid >> 5;

    const int warpsPerStream = N / ROWS_PER_WARP;     // 2048
    const int gwarp  = blockIdx.x * WARPS + wib;
    const int stream = (gwarp >= warpsPerStream) ? 1 : 0;
    const int wloc   = gwarp - stream * warpsPerStream;
    const int base   = wloc * ROWS_PER_WARP;          // first row of this warp

    const int*   b  = stream ? b2 : b1;
    const float* z  = stream ? z2 : z1;
    const float* gS = stream ? g2 : g1;               // self pairing
    const float* gC = stream ? g1 : g2;               // cross pairing

    const int row  = base + lane;                     // my row
    const int gidx = b[row];                          // coalesced
    const float4* gS4 = reinterpret_cast<const float4*>(gS) + (size_t)gidx * 64;
    const float4* gC4 = reinterpret_cast<const float4*>(gC) + (size_t)gidx * 64;
    const float4* z4  = reinterpret_cast<const float4*>(z) + (size_t)base * 64;

    unsigned int smem_warp;
    {
        void* p = (void*)(zbuf + wib * 2 * WARP_BUF_Q);
        smem_warp = (unsigned int)__cvta_generic_to_shared(p);
    }

    // stage chunk c of this warp's 32 rows into buffer buf (warp-level, coalesced)
    auto stage = [&](int c, int buf) {
        const unsigned int sbase = smem_warp + (unsigned int)buf * WARP_BUF_Q * 16u;
        #pragma unroll
        for (int j = 0; j < 8; ++j) {
            const int i  = j * 32 + lane;             // 0..255
            const int rl = i >> 3;                    // row within warp
            const int q  = i & 7;
            const int sq = q ^ (rl & 7);              // XOR swizzle, no padding
            cp_async16(sbase + (unsigned int)(rl * CHUNK_Q + sq) * 16u,
                       (const void*)(z4 + (size_t)rl * 64 + c * CHUNK_Q + q));
        }
        cp_commit();
    };

    unsigned long long vS = 0, vC = 0;                // packed (even,odd) partials

    stage(0, 0);
    #pragma unroll
    for (int c = 0; c < NCHUNK; ++c) {
        if (c + 1 < NCHUNK) stage(c + 1, (c + 1) & 1);
        if (c + 1 < NCHUNK) cp_wait<1>(); else cp_wait<0>();
        __syncwarp();

        const float4* zb = zbuf + wib * 2 * WARP_BUF_Q + (c & 1) * WARP_BUF_Q
                         + lane * CHUNK_Q;
        #pragma unroll
        for (int q = 0; q < CHUNK_Q; ++q) {
            // zb[q ^ (lane&7)] holds z element q of my row (store-side swizzle).
            // Pair it with g element q  -> correct dot AND warp-uniform g address
            // (broadcast when gidx matches across lanes, which sorted batch gives).
            float4 zv = zb[q ^ (lane & 7)];
            float4 sv = __ldg(gS4 + c * CHUNK_Q + q);
            float4 cv = __ldg(gC4 + c * CHUNK_Q + q);
            unsigned long long zlo = pack2(zv.x, zv.y), zhi = pack2(zv.z, zv.w);
            vS = fma2(zlo, pack2(sv.x, sv.y), vS);
            vS = fma2(zhi, pack2(sv.z, sv.w), vS);
            vC = fma2(zlo, pack2(cv.x, cv.y), vC);
            vC = fma2(zhi, pack2(cv.z, cv.w), vC);
        }
        __syncwarp();                                 // buffer reuse guard
    }

    float sx, sy, cx, cy;
    unpack2(vS, sx, sy); unpack2(vC, cx, cy);
    const float dS = sx + sy, dC = cx + cy;
    const float t = softplusf(-dC) - softplusf(-dS);  // LOG2 cancels in the diff
    double accd = (double)t * (double)t;

    #pragma unroll
    for (int off = 16; off > 0; off >>= 1)
        accd += __shfl_xor_sync(0xFFFFFFFFu, accd, off);

    __shared__ double sh[WARPS];
    __shared__ int s_isLast;
    if (lane == 0) sh[wib] = accd;
    __syncthreads();

    if (tid == 0) {
        double s = sh[0] + sh[1] + sh[2] + sh[3];
        g_part[blockIdx.x] = s;
        __threadfence();
        unsigned int old = atomicAdd(&g_count, 1u);
        s_isLast = (old == gridDim.x - 1) ? 1 : 0;
    }
    __syncthreads();

    if (s_isLast) {
        const int grid = gridDim.x;
        const int half = grid >> 1;                   // first half = stream 0
        double s0 = 0.0, s1 = 0.0;
        volatile double* vp = g_part;
        for (int i = tid; i < grid; i += THREADS) {
            double v = vp[i];
            if (i < half) s0 += v; else s1 += v;
        }
        #pragma unroll
        for (int off = 16; off > 0; off >>= 1) {
            s0 += __shfl_xor_sync(0xFFFFFFFFu, s0, off);
            s1 += __shfl_xor_sync(0xFFFFFFFFu, s1, off);
        }
        __shared__ double r0[WARPS], r1[WARPS];
        if (lane == 0) { r0[wib] = s0; r1[wib] = s1; }
        __syncthreads();
        if (tid == 0) {
            double S0 = r0[0] + r0[1] + r0[2] + r0[3];
            double S1 = r1[0] + r1[1] + r1[2] + r1[3];
            out[0] = (float)(sqrt(S0) + sqrt(S1));
            atomicExch(&g_count, 0u);                 // reset for next graph replay
        }
    }
}

extern "C" void kernel_launch(void* const* d_in, const int* in_sizes, int n_in,
                              void* d_out, int out_size) {
    const int*   b1 = (const int*)d_in[0];
    const int*   b2 = (const int*)d_in[1];
    const float* z1 = (const float*)d_in[2];
    const float* z2 = (const float*)d_in[3];
    const float* g1 = (const float*)d_in[4];
    const float* g2 = (const float*)d_in[5];
    float* out = (float*)d_out;

    const int N = in_sizes[0];                        // 65536
    const int rowsPerBlock = ROWS_PER_WARP * WARPS;   // 128
    const int grid = (2 * N) / rowsPerBlock;          // 1024
    const int smemBytes = WARPS * 2 * WARP_BUF_Q * 16;  // 32,768 B

    sat_fused_kernel<<<grid, THREADS, smemBytes>>>(b1, b2, z1, z2, g1, g2, out, N);
}

// round 8
// speedup vs baseline: 1.2846x; 1.0224x over previous
#include <cuda_runtime.h>
#include <math.h>

#define THREADS         128
#define WARPS           4
#define ROWS_PER_WARP   16
#define CHUNK_Q         8                   // float4 per chunk per row
#define NCHUNK          8                   // 8 x 32 floats = D=256
#define WARP_BUF_Q      (ROWS_PER_WARP * CHUNK_Q)   // 128 float4 = 2KB
#define MAX_BLOCKS      8192

__device__ double g_part[MAX_BLOCKS];
__device__ unsigned int g_count;            // zero at load; last block resets -> replay-safe

__device__ __forceinline__ float softplusf(float x) {
    return fmaxf(x, 0.0f) + log1pf(expf(-fabsf(x)));
}

// packed f32x2 helpers
__device__ __forceinline__ unsigned long long pack2(float lo, float hi) {
    unsigned long long r;
    asm("mov.b64 %0, {%1, %2};" : "=l"(r) : "f"(lo), "f"(hi));
    return r;
}
__device__ __forceinline__ void unpack2(unsigned long long v, float& lo, float& hi) {
    asm("mov.b64 {%0, %1}, %2;" : "=f"(lo), "=f"(hi) : "l"(v));
}
__device__ __forceinline__ unsigned long long fma2(unsigned long long a,
                                                   unsigned long long b,
                                                   unsigned long long c) {
    unsigned long long d;
    asm("fma.rn.f32x2 %0, %1, %2, %3;" : "=l"(d) : "l"(a), "l"(b), "l"(c));
    return d;
}

__device__ __forceinline__ void cp_async16(unsigned int smem_addr, const void* gptr) {
    asm volatile("cp.async.cg.shared.global [%0], [%1], 16;" :: "r"(smem_addr), "l"(gptr));
}
__device__ __forceinline__ void cp_commit() {
    asm volatile("cp.async.commit_group;");
}
template <int N_>
__device__ __forceinline__ void cp_wait() {
    asm volatile("cp.async.wait_group %0;" :: "n"(N_));
}

__global__ void __launch_bounds__(THREADS, 12) sat_fused_kernel(
    const int* __restrict__ b1, const int* __restrict__ b2,
    const float* __restrict__ z1, const float* __restrict__ z2,
    const float* __restrict__ g1, const float* __restrict__ g2,
    float* __restrict__ out, int N)
{
    extern __shared__ float4 zbuf[];                  // [WARPS][2][WARP_BUF_Q]
    const int tid  = threadIdx.x;
    const int lane = tid & 31;
    const int wib  = tid >> 5;

    const int warpsPerStream = N / ROWS_PER_WARP;     // 4096
    const int gwarp  = blockIdx.x * WARPS + wib;
    const int stream = (gwarp >= warpsPerStream) ? 1 : 0;
    const int wloc   = gwarp - stream * warpsPerStream;
    const int base   = wloc * ROWS_PER_WARP;          // first row of this warp

    const int*   b  = stream ? b2 : b1;
    const float* z  = stream ? z2 : z1;
    const float* gS = stream ? g2 : g1;               // self pairing
    const float* gC = stream ? g1 : g2;               // cross pairing

    // Each lane handles HALF a row: row = base + (lane>>1), columns half*16..+15
    const int rl   = lane >> 1;                       // row within warp (0..15)
    const int half = lane & 1;                        // which 4-float4 half
    const int gidx = b[base + rl];
    const float4* gS4 = reinterpret_cast<const float4*>(gS) + (size_t)gidx * 64;
    const float4* gC4 = reinterpret_cast<const float4*>(gC) + (size_t)gidx * 64;
    const float4* z4  = reinterpret_cast<const float4*>(z) + (size_t)base * 64;

    unsigned int smem_warp;
    {
        void* p = (void*)(zbuf + wib * 2 * WARP_BUF_Q);
        smem_warp = (unsigned int)__cvta_generic_to_shared(p);
    }

    // stage chunk c (16 rows x 8 float4, swizzled) into buffer buf
    auto stage = [&](int c, int buf) {
        const unsigned int sbase = smem_warp + (unsigned int)buf * WARP_BUF_Q * 16u;
        #pragma unroll
        for (int j = 0; j < 4; ++j) {
            const int i  = j * 32 + lane;             // 0..127
            const int rr = i >> 3;                    // row 0..15
            const int q  = i & 7;
            const int sq = q ^ (rr & 7);              // XOR swizzle
            cp_async16(sbase + (unsigned int)(rr * CHUNK_Q + sq) * 16u,
                       (const void*)(z4 + (size_t)rr * 64 + c * CHUNK_Q + q));
        }
        cp_commit();
    };

    unsigned long long vS = 0, vC = 0;                // packed (even,odd) partials

    stage(0, 0);
    #pragma unroll
    for (int c = 0; c < NCHUNK; ++c) {
        if (c + 1 < NCHUNK) stage(c + 1, (c + 1) & 1);
        if (c + 1 < NCHUNK) cp_wait<1>(); else cp_wait<0>();
        __syncwarp();

        const float4* zb = zbuf + wib * 2 * WARP_BUF_Q + (c & 1) * WARP_BUF_Q
                         + rl * CHUNK_Q;
        #pragma unroll
        for (int k = 0; k < 4; ++k) {
            const int q = half * 4 + k;               // my column quarter
            float4 zv = zb[q ^ (rl & 7)];             // de-swizzle = z element q
            float4 sv = __ldg(gS4 + c * CHUNK_Q + q);
            float4 cv = __ldg(gC4 + c * CHUNK_Q + q);
            unsigned long long zlo = pack2(zv.x, zv.y), zhi = pack2(zv.z, zv.w);
            vS = fma2(zlo, pack2(sv.x, sv.y), vS);
            vS = fma2(zhi, pack2(sv.z, sv.w), vS);
            vC = fma2(zlo, pack2(cv.x, cv.y), vC);
            vC = fma2(zhi, pack2(cv.z, cv.w), vC);
        }
        __syncwarp();                                 // buffer reuse guard
    }

    // combine the two half-row partials (lanes 2r and 2r+1)
    vS = fma2(pack2(1.f, 1.f), __shfl_xor_sync(0xFFFFFFFFu, vS, 1), vS);
    vC = fma2(pack2(1.f, 1.f), __shfl_xor_sync(0xFFFFFFFFu, vC, 1), vC);

    float sx, sy, cx, cy;
    unpack2(vS, sx, sy); unpack2(vC, cx, cy);
    const float dS = sx + sy, dC = cx + cy;
    float t = softplusf(-dC) - softplusf(-dS);        // LOG2 cancels in the diff
    if (half) t = 0.0f;                               // row counted once (even lane)
    double accd = (double)t * (double)t;

    #pragma unroll
    for (int off = 16; off > 0; off >>= 1)
        accd += __shfl_xor_sync(0xFFFFFFFFu, accd, off);

    __shared__ double sh[WARPS];
    __shared__ int s_isLast;
    if (lane == 0) sh[wib] = accd;
    __syncthreads();

    if (tid == 0) {
        double s = sh[0] + sh[1] + sh[2] + sh[3];
        g_part[blockIdx.x] = s;
        __threadfence();
        unsigned int old = atomicAdd(&g_count, 1u);
        s_isLast = (old == gridDim.x - 1) ? 1 : 0;
    }
    __syncthreads();

    if (s_isLast) {
        const int grid = gridDim.x;
        const int halfg = grid >> 1;                  // first half = stream 0
        double s0 = 0.0, s1 = 0.0;
        volatile double* vp = g_part;
        for (int i = tid; i < grid; i += THREADS) {
            double v = vp[i];
            if (i < halfg) s0 += v; else s1 += v;
        }
        #pragma unroll
        for (int off = 16; off > 0; off >>= 1) {
            s0 += __shfl_xor_sync(0xFFFFFFFFu, s0, off);
            s1 += __shfl_xor_sync(0xFFFFFFFFu, s1, off);
        }
        __shared__ double r0[WARPS], r1[WARPS];
        if (lane == 0) { r0[wib] = s0; r1[wib] = s1; }
        __syncthreads();
        if (tid == 0) {
            double S0 = r0[0] + r0[1] + r0[2] + r0[3];
            double S1 = r1[0] + r1[1] + r1[2] + r1[3];
            out[0] = (float)(sqrt(S0) + sqrt(S1));
            atomicExch(&g_count, 0u);                 // reset for next graph replay
        }
    }
}

extern "C" void kernel_launch(void* const* d_in, const int* in_sizes, int n_in,
                              void* d_out, int out_size) {
    const int*   b1 = (const int*)d_in[0];
    const int*   b2 = (const int*)d_in[1];
    const float* z1 = (const float*)d_in[2];
    const float* z2 = (const float*)d_in[3];
    const float* g1 = (const float*)d_in[4];
    const float* g2 = (const float*)d_in[5];
    float* out = (float*)d_out;

    const int N = in_sizes[0];                        // 65536
    const int rowsPerBlock = ROWS_PER_WARP * WARPS;   // 64
    const int grid = (2 * N) / rowsPerBlock;          // 2048
    const int smemBytes = WARPS * 2 * WARP_BUF_Q * 16;  // 16,384 B

    sat_fused_kernel<<<grid, THREADS, smemBytes>>>(b1, b2, z1, z2, g1, g2, out, N);
}